// round 14
// baseline (speedup 1.0000x reference)
#include <cuda_runtime.h>
#include <cuda_fp16.h>
#include <cstdint>
#include <cstddef>

// ---------------------------------------------------------------------------
// Problem constants
// ---------------------------------------------------------------------------
#define TOKENS 4096   // M
#define IN_F   4096   // K
#define OUT_F  11008  // N

// GEMM tiling: ONE 512-thread CTA/SM, 16 warps (4m x 4n), warp tile m32n64.
// BM=128, BN=256, BK=128, 2-stage ping-pong, single-thread bulk copies from
// pre-swizzled tiled gmem.
#define BM 128
#define BN 256
#define BK 128
#define KTILES (IN_F / BK)   // 32
#define NTHREADS 512

#define A_STAGE_BYTES 32768                   // 2 x (128 rows x 128B) k-subtiles
#define B_STAGE_BYTES 65536                   // 2 x (256 rows x 128B) k-subtiles
#define STAGE_BYTES   (A_STAGE_BYTES + B_STAGE_BYTES)   // 98304
#define SMEM_TOTAL    (2 * STAGE_BYTES)                 // 196608 <= 228KB

// ---------------------------------------------------------------------------
// Device scratch (static — no cudaMalloc anywhere)
// g_xh: [mb(32)][k64(64)][16KB image: 128 rows x 128B, swizzled]
// g_q : [nb(43)][k64(64)][32KB image: 256 rows x 128B, swizzled]
// ---------------------------------------------------------------------------
__device__ __half  g_q[(size_t)OUT_F * IN_F];
__device__ __half  g_xh[(size_t)TOKENS * IN_F];
__device__ double  g_partial[1024];
__device__ float   g_alpha;

// ---------------------------------------------------------------------------
// PTX helpers (baseline compute_103 — cp.async.bulk + mbarrier are sm_90 PTX)
// ---------------------------------------------------------------------------
__device__ __forceinline__ uint32_t smem_u32(const void* p) {
    uint32_t a;
    asm("{ .reg .u64 t; cvta.to.shared.u64 t, %1; cvt.u32.u64 %0, t; }"
        : "=r"(a) : "l"(p));
    return a;
}

__device__ __forceinline__ void bulk_cp(uint32_t dst, const void* src,
                                        uint32_t bytes, uint32_t mbar) {
    asm volatile(
        "{ .reg .u64 g; cvta.to.global.u64 g, %1; "
        "cp.async.bulk.shared::cta.global.mbarrier::complete_tx::bytes "
        "[%0], [g], %2, [%3]; }"
        :: "r"(dst), "l"(src), "r"(bytes), "r"(mbar) : "memory");
}

#define MBAR_INIT(a, c) \
    asm volatile("mbarrier.init.shared.b64 [%0], %1;" :: "r"(a), "r"((uint32_t)(c)) : "memory")
#define MBAR_EXPECT_TX(a, b) \
    asm volatile("mbarrier.arrive.expect_tx.shared.b64 _, [%0], %1;" \
                 :: "r"(a), "r"((uint32_t)(b)) : "memory")
#define FENCE_PROXY_ASYNC() \
    asm volatile("fence.proxy.async.shared::cta;" ::: "memory")

__device__ __forceinline__ void mbar_wait(uint32_t addr, uint32_t parity) {
    asm volatile(
        "{\n\t"
        ".reg .pred P;\n\t"
        "WL_%=:\n\t"
        "mbarrier.try_wait.parity.acquire.cta.shared::cta.b64 P, [%0], %1, 0x989680;\n\t"
        "@P bra WD_%=;\n\t"
        "bra WL_%=;\n\t"
        "WD_%=:\n\t"
        "}"
        :: "r"(addr), "r"(parity) : "memory");
}

__device__ __forceinline__ void ldsm_x4(uint32_t& r0, uint32_t& r1,
                                        uint32_t& r2, uint32_t& r3, uint32_t a) {
    asm volatile("ldmatrix.sync.aligned.m8n8.x4.shared.b16 {%0,%1,%2,%3}, [%4];"
                 : "=r"(r0), "=r"(r1), "=r"(r2), "=r"(r3) : "r"(a));
}

__device__ __forceinline__ void mma16816(float& c0, float& c1, float& c2, float& c3,
                                         uint32_t a0, uint32_t a1, uint32_t a2, uint32_t a3,
                                         uint32_t b0, uint32_t b1) {
    asm volatile(
        "mma.sync.aligned.m16n8k16.row.col.f32.f16.f16.f32 "
        "{%0,%1,%2,%3}, {%4,%5,%6,%7}, {%8,%9}, {%0,%1,%2,%3};"
        : "+f"(c0), "+f"(c1), "+f"(c2), "+f"(c3)
        : "r"(a0), "r"(a1), "r"(a2), "r"(a3), "r"(b0), "r"(b1));
}

// SW128 swizzle for 128-byte rows: 16B chunk c (0..7), row r (any count).
__device__ __forceinline__ uint32_t swz128(uint32_t row, uint32_t c) {
    return row * 128u + ((c ^ (row & 7u)) << 4);
}

// ---------------------------------------------------------------------------
// Kernel 1: deterministic |W| partial sums (fp64 accumulators)
// ---------------------------------------------------------------------------
__global__ void reduce_abs_kernel(const float* __restrict__ w) {
    __shared__ double sh[256];
    const size_t n4 = (size_t)OUT_F * IN_F / 4;
    const float4* w4 = (const float4*)w;
    double acc = 0.0;
    for (size_t i = (size_t)blockIdx.x * 256 + threadIdx.x; i < n4;
         i += (size_t)1024 * 256) {
        float4 v = w4[i];
        acc += (double)fabsf(v.x) + (double)fabsf(v.y) +
               (double)fabsf(v.z) + (double)fabsf(v.w);
    }
    int tid = threadIdx.x;
    sh[tid] = acc;
    __syncthreads();
    for (int s = 128; s > 0; s >>= 1) {
        if (tid < s) sh[tid] += sh[tid + s];
        __syncthreads();
    }
    if (tid == 0) g_partial[blockIdx.x] = sh[0];
}

__global__ void finalize_alpha_kernel() {
    __shared__ double sh[256];
    int tid = threadIdx.x;
    double a = g_partial[tid] + g_partial[tid + 256] +
               g_partial[tid + 512] + g_partial[tid + 768];
    sh[tid] = a;
    __syncthreads();
    for (int s = 128; s > 0; s >>= 1) {
        if (tid < s) sh[tid] += sh[tid + s];
        __syncthreads();
    }
    if (tid == 0) g_alpha = (float)(sh[0] / ((double)OUT_F * (double)IN_F));
}

// ---------------------------------------------------------------------------
// Kernel 3: ternary quantize W -> fp16 tiles: [nb256][k64][32KB 256-row image]
// One thread per 16B chunk (8 weights). 43*64*2048 chunks total.
// ---------------------------------------------------------------------------
__global__ void quantize_kernel(const float* __restrict__ w) {
    const float a = g_alpha;
    uint32_t id = blockIdx.x * 256 + threadIdx.x;   // < 43*64*2048
    uint32_t nb = id >> 17;            // 256-row block (0..42)
    uint32_t t = id & 131071;
    uint32_t kimg = t >> 11;           // 64-k image (0..63)
    uint32_t v = t & 2047;
    uint32_t r = v >> 3;               // row in image (0..255)
    uint32_t c = v & 7;                // 16B chunk in row (0..7)
    const float* src = w + ((size_t)(nb * 256 + r)) * IN_F + kimg * 64 + c * 8;
    float4 v0 = *(const float4*)src;
    float4 v1 = *(const float4*)(src + 4);
    __half h[8];
    h[0] = __float2half_rn((v0.x > a) ? 1.0f : ((v0.x < -a) ? -1.0f : 0.0f));
    h[1] = __float2half_rn((v0.y > a) ? 1.0f : ((v0.y < -a) ? -1.0f : 0.0f));
    h[2] = __float2half_rn((v0.z > a) ? 1.0f : ((v0.z < -a) ? -1.0f : 0.0f));
    h[3] = __float2half_rn((v0.w > a) ? 1.0f : ((v0.w < -a) ? -1.0f : 0.0f));
    h[4] = __float2half_rn((v1.x > a) ? 1.0f : ((v1.x < -a) ? -1.0f : 0.0f));
    h[5] = __float2half_rn((v1.y > a) ? 1.0f : ((v1.y < -a) ? -1.0f : 0.0f));
    h[6] = __float2half_rn((v1.z > a) ? 1.0f : ((v1.z < -a) ? -1.0f : 0.0f));
    h[7] = __float2half_rn((v1.w > a) ? 1.0f : ((v1.w < -a) ? -1.0f : 0.0f));
    char* dst = (char*)g_q + (((size_t)nb * 64 + kimg) << 15) + swz128(r, c);
    *(uint4*)dst = *(const uint4*)h;
}

// ---------------------------------------------------------------------------
// Kernel 4: x -> fp16 tiles: [mb128][k64][16KB 128-row image]
// ---------------------------------------------------------------------------
__global__ void convert_x_kernel(const float* __restrict__ x) {
    uint32_t id = blockIdx.x * 256 + threadIdx.x;   // < 32*65536
    uint32_t mb = id >> 16;
    uint32_t t = id & 65535;
    uint32_t kimg = t >> 10;
    uint32_t v = t & 1023;
    uint32_t r = v >> 3;
    uint32_t c = v & 7;
    const float* src = x + ((size_t)(mb * 128 + r)) * IN_F + kimg * 64 + c * 8;
    float4 v0 = *(const float4*)src;
    float4 v1 = *(const float4*)(src + 4);
    __half h[8];
    h[0] = __float2half_rn(v0.x); h[1] = __float2half_rn(v0.y);
    h[2] = __float2half_rn(v0.z); h[3] = __float2half_rn(v0.w);
    h[4] = __float2half_rn(v1.x); h[5] = __float2half_rn(v1.y);
    h[6] = __float2half_rn(v1.z); h[7] = __float2half_rn(v1.w);
    char* dst = (char*)g_xh + (((size_t)mb * 64 + kimg) << 14) + swz128(r, c);
    *(uint4*)dst = *(const uint4*)h;
}

// ---------------------------------------------------------------------------
// Kernel 5: fp16 HMMA GEMM. 512 threads, 16 warps m32n64, BK=128, 2-stage
// ping-pong, bulk copies (A 32KB + B 64KB per stage, one mbarrier).
// out[m, n] = (sum_k xh[m,k] * q[n,k]) * scale[n] + bias[n]
// ---------------------------------------------------------------------------
__global__ void __launch_bounds__(NTHREADS, 1)
gemm_kernel(float* __restrict__ out, const float* __restrict__ scale,
            const float* __restrict__ bias) {
    extern __shared__ __align__(128) char smem[];
    __shared__ __align__(8) uint64_t mbar_s[2];
    const uint32_t sb = smem_u32(smem);
    uint32_t mb[2];
    mb[0] = smem_u32(&mbar_s[0]);
    mb[1] = smem_u32(&mbar_s[1]);

    const int tid = threadIdx.x;
    const int lane = tid & 31;
    const int wid = tid >> 5;
    const int warp_m = (wid & 3) * 32;
    const int warp_n = (wid >> 2) * 64;

    const int m0 = blockIdx.x * BM;   // m fastest -> q n-tiles L2-shared
    const int n0 = blockIdx.y * BN;

    // Per-kt (BK=128) sources: A = 2 consecutive 16KB images, B = 2
    // consecutive 32KB images -> single contiguous bulk copies.
    const char* aT = (const char*)g_xh + ((size_t)blockIdx.x << 20);       // mb*64<<14
    const char* bT = (const char*)g_q + ((size_t)blockIdx.y * 64 << 15);

    // ldsm swizzled offsets at ks=0; per-ks: XOR (ks&3)<<5, plus k-subtile
    // base (+16KB for A, +32KB for B when ks>=4).
    uint32_t offA[2], offB[4];
#pragma unroll
    for (int mt = 0; mt < 2; mt++)
        offA[mt] = swz128((uint32_t)(warp_m + mt * 16 + (lane & 15)),
                          (uint32_t)(lane >> 4));
#pragma unroll
    for (int ng = 0; ng < 4; ng++)
        offB[ng] = A_STAGE_BYTES +
                   swz128((uint32_t)(warp_n + ng * 16 + ((lane >> 4) << 3) + (lane & 7)),
                          (uint32_t)((lane >> 3) & 1));

    float acc[2][8][4];
#pragma unroll
    for (int mt = 0; mt < 2; mt++)
#pragma unroll
        for (int nt = 0; nt < 8; nt++)
#pragma unroll
            for (int j = 0; j < 4; j++) acc[mt][nt][j] = 0.0f;

    if (tid == 0) {
        MBAR_INIT(mb[0], 1);
        MBAR_INIT(mb[1], 1);
    }
    __syncthreads();

    // Prologue: stage 0 <- kt 0
    if (tid == 0) {
        FENCE_PROXY_ASYNC();
        MBAR_EXPECT_TX(mb[0], STAGE_BYTES);
        bulk_cp(sb, aT, A_STAGE_BYTES, mb[0]);
        bulk_cp(sb + A_STAGE_BYTES, bT, B_STAGE_BYTES, mb[0]);
    }

    for (int kt = 0; kt < KTILES; kt++) {
        __syncthreads();   // all warps done reading stage (kt+1)&1 (from kt-1)

        if (tid == 0 && kt + 1 < KTILES) {
            FENCE_PROXY_ASYNC();
            const int s = (kt + 1) & 1;
            MBAR_EXPECT_TX(mb[s], STAGE_BYTES);
            bulk_cp(sb + s * STAGE_BYTES,
                    aT + ((size_t)(kt + 1) << 15), A_STAGE_BYTES, mb[s]);
            bulk_cp(sb + s * STAGE_BYTES + A_STAGE_BYTES,
                    bT + ((size_t)(kt + 1) << 16), B_STAGE_BYTES, mb[s]);
        }

        mbar_wait(mb[kt & 1], (kt >> 1) & 1);
        const uint32_t stage = sb + (kt & 1) * STAGE_BYTES;

#pragma unroll 1
        for (int ks = 0; ks < 8; ks++) {
            const uint32_t kx = (uint32_t)((ks & 3) << 5);
            const uint32_t abase = stage + ((uint32_t)(ks >> 2) << 14);
            const uint32_t bbase = stage + ((uint32_t)(ks >> 2) << 15);
            uint32_t af[2][4];
            uint32_t bf[8][2];
#pragma unroll
            for (int mt = 0; mt < 2; mt++)
                ldsm_x4(af[mt][0], af[mt][1], af[mt][2], af[mt][3],
                        abase + (offA[mt] ^ kx));
#pragma unroll
            for (int ng = 0; ng < 4; ng++) {
                uint32_t r0, r1, r2, r3;
                ldsm_x4(r0, r1, r2, r3, bbase + (offB[ng] ^ kx));
                bf[2 * ng + 0][0] = r0; bf[2 * ng + 0][1] = r1;
                bf[2 * ng + 1][0] = r2; bf[2 * ng + 1][1] = r3;
            }
#pragma unroll
            for (int mt = 0; mt < 2; mt++)
#pragma unroll
                for (int nt = 0; nt < 8; nt++)
                    mma16816(acc[mt][nt][0], acc[mt][nt][1],
                             acc[mt][nt][2], acc[mt][nt][3],
                             af[mt][0], af[mt][1], af[mt][2], af[mt][3],
                             bf[nt][0], bf[nt][1]);
        }
    }

    // Epilogue: scale + bias, direct fp32 stores.
#pragma unroll
    for (int nt = 0; nt < 8; nt++) {
        const int c = n0 + warp_n + nt * 8 + (lane & 3) * 2;
        const float s0 = __ldg(scale + c), s1 = __ldg(scale + c + 1);
        const float b0 = __ldg(bias + c), b1 = __ldg(bias + c + 1);
#pragma unroll
        for (int mt = 0; mt < 2; mt++) {
            const int r0 = m0 + warp_m + mt * 16 + (lane >> 2);
            float2 v0 = {acc[mt][nt][0] * s0 + b0, acc[mt][nt][1] * s1 + b1};
            float2 v1 = {acc[mt][nt][2] * s0 + b0, acc[mt][nt][3] * s1 + b1};
            *(float2*)(out + (size_t)r0 * OUT_F + c) = v0;
            *(float2*)(out + (size_t)(r0 + 8) * OUT_F + c) = v1;
        }
    }
}

// ---------------------------------------------------------------------------
// kernel_launch
// ---------------------------------------------------------------------------
extern "C" void kernel_launch(void* const* d_in, const int* in_sizes, int n_in,
                              void* d_out, int out_size) {
    const float* x      = (const float*)d_in[0];  // (4096, 4096)
    const float* weight = (const float*)d_in[1];  // (11008, 4096)
    const float* scale  = (const float*)d_in[2];  // (11008, 1)
    const float* bias   = (const float*)d_in[3];  // (11008,)
    float* out = (float*)d_out;                   // (4096, 11008)
    (void)in_sizes; (void)n_in; (void)out_size;

    reduce_abs_kernel<<<1024, 256>>>(weight);
    finalize_alpha_kernel<<<1, 256>>>();
    quantize_kernel<<<43 * 64 * 8, 256>>>(weight);       // 43*64*2048 / 256
    convert_x_kernel<<<32 * 64 * 4, 256>>>(x);           // 32*64*1024 / 256

    cudaFuncSetAttribute(gemm_kernel,
                         cudaFuncAttributeMaxDynamicSharedMemorySize, SMEM_TOTAL);
    dim3 grid(TOKENS / BM, OUT_F / BN);  // (32, 43)
    gemm_kernel<<<grid, NTHREADS, SMEM_TOTAL>>>(out, scale, bias);
}

// round 15
// speedup vs baseline: 1.0182x; 1.0182x over previous
#include <cuda_runtime.h>
#include <cuda_fp16.h>
#include <cstdint>
#include <cstddef>

// ---------------------------------------------------------------------------
// Problem constants
// ---------------------------------------------------------------------------
#define TOKENS 4096   // M
#define IN_F   4096   // K
#define OUT_F  11008  // N

// GEMM tiling: CTA 128x128, 8 warps (2m x 4n), warp tile m64n32, 2 CTAs/SM.
// R11 structure; per-kt __syncthreads replaced by full/empty mbarrier
// producer-consumer pipeline (warps decoupled).
#define BM 128
#define BN 128
#define BK 64
#define KTILES (IN_F / BK)   // 64
#define STAGES 3

#define A_TILE_BYTES 16384                    // 128 rows x 128 B
#define B_TILE_BYTES 16384
#define STAGE_BYTES  (A_TILE_BYTES + B_TILE_BYTES)      // 32768
#define SMEM_TOTAL   (STAGES * STAGE_BYTES)             // 98304 -> 2 CTAs/SM

// ---------------------------------------------------------------------------
// Device scratch (static — no cudaMalloc anywhere)
// Tiled layout: [row_block][kt][16KB tile], tile = swizzled smem image.
// ---------------------------------------------------------------------------
__device__ __half  g_q[(size_t)OUT_F * IN_F];    // ternary weights, tiled+swizzled
__device__ __half  g_xh[(size_t)TOKENS * IN_F];  // fp16(x), tiled+swizzled
__device__ double  g_partial[1024];
__device__ float   g_alpha;

// ---------------------------------------------------------------------------
// PTX helpers (baseline compute_103 — cp.async.bulk + mbarrier are sm_90 PTX)
// ---------------------------------------------------------------------------
__device__ __forceinline__ uint32_t smem_u32(const void* p) {
    uint32_t a;
    asm("{ .reg .u64 t; cvta.to.shared.u64 t, %1; cvt.u32.u64 %0, t; }"
        : "=r"(a) : "l"(p));
    return a;
}

__device__ __forceinline__ void bulk_cp(uint32_t dst, const void* src,
                                        uint32_t bytes, uint32_t mbar) {
    asm volatile(
        "{ .reg .u64 g; cvta.to.global.u64 g, %1; "
        "cp.async.bulk.shared::cta.global.mbarrier::complete_tx::bytes "
        "[%0], [g], %2, [%3]; }"
        :: "r"(dst), "l"(src), "r"(bytes), "r"(mbar) : "memory");
}

#define MBAR_INIT(a, c) \
    asm volatile("mbarrier.init.shared.b64 [%0], %1;" :: "r"(a), "r"((uint32_t)(c)) : "memory")
#define MBAR_EXPECT_TX(a, b) \
    asm volatile("mbarrier.arrive.expect_tx.shared.b64 _, [%0], %1;" \
                 :: "r"(a), "r"((uint32_t)(b)) : "memory")
#define MBAR_ARRIVE(a) \
    asm volatile("mbarrier.arrive.shared.b64 _, [%0];" :: "r"(a) : "memory")
#define FENCE_PROXY_ASYNC() \
    asm volatile("fence.proxy.async.shared::cta;" ::: "memory")

__device__ __forceinline__ void mbar_wait(uint32_t addr, uint32_t parity) {
    asm volatile(
        "{\n\t"
        ".reg .pred P;\n\t"
        "WL_%=:\n\t"
        "mbarrier.try_wait.parity.acquire.cta.shared::cta.b64 P, [%0], %1, 0x989680;\n\t"
        "@P bra WD_%=;\n\t"
        "bra WL_%=;\n\t"
        "WD_%=:\n\t"
        "}"
        :: "r"(addr), "r"(parity) : "memory");
}

__device__ __forceinline__ void ldsm_x4(uint32_t& r0, uint32_t& r1,
                                        uint32_t& r2, uint32_t& r3, uint32_t a) {
    asm volatile("ldmatrix.sync.aligned.m8n8.x4.shared.b16 {%0,%1,%2,%3}, [%4];"
                 : "=r"(r0), "=r"(r1), "=r"(r2), "=r"(r3) : "r"(a));
}

__device__ __forceinline__ void mma16816(float& c0, float& c1, float& c2, float& c3,
                                         uint32_t a0, uint32_t a1, uint32_t a2, uint32_t a3,
                                         uint32_t b0, uint32_t b1) {
    asm volatile(
        "mma.sync.aligned.m16n8k16.row.col.f32.f16.f16.f32 "
        "{%0,%1,%2,%3}, {%4,%5,%6,%7}, {%8,%9}, {%0,%1,%2,%3};"
        : "+f"(c0), "+f"(c1), "+f"(c2), "+f"(c3)
        : "r"(a0), "r"(a1), "r"(a2), "r"(a3), "r"(b0), "r"(b1));
}

// SW128 swizzle for 128-byte rows: 16B chunk c (0..7), row r.
__device__ __forceinline__ uint32_t swz128(uint32_t row, uint32_t c) {
    return row * 128u + ((c ^ (row & 7u)) << 4);
}

// ---------------------------------------------------------------------------
// Kernel 1: deterministic |W| partial sums (fp64 accumulators)
// ---------------------------------------------------------------------------
__global__ void reduce_abs_kernel(const float* __restrict__ w) {
    __shared__ double sh[256];
    const size_t n4 = (size_t)OUT_F * IN_F / 4;
    const float4* w4 = (const float4*)w;
    double acc = 0.0;
    for (size_t i = (size_t)blockIdx.x * 256 + threadIdx.x; i < n4;
         i += (size_t)1024 * 256) {
        float4 v = w4[i];
        acc += (double)fabsf(v.x) + (double)fabsf(v.y) +
               (double)fabsf(v.z) + (double)fabsf(v.w);
    }
    int tid = threadIdx.x;
    sh[tid] = acc;
    __syncthreads();
    for (int s = 128; s > 0; s >>= 1) {
        if (tid < s) sh[tid] += sh[tid + s];
        __syncthreads();
    }
    if (tid == 0) g_partial[blockIdx.x] = sh[0];
}

__global__ void finalize_alpha_kernel() {
    __shared__ double sh[256];
    int tid = threadIdx.x;
    double a = g_partial[tid] + g_partial[tid + 256] +
               g_partial[tid + 512] + g_partial[tid + 768];
    sh[tid] = a;
    __syncthreads();
    for (int s = 128; s > 0; s >>= 1) {
        if (tid < s) sh[tid] += sh[tid + s];
        __syncthreads();
    }
    if (tid == 0) g_alpha = (float)(sh[0] / ((double)OUT_F * (double)IN_F));
}

// ---------------------------------------------------------------------------
// Kernel 3: ternary quantize W -> fp16 tiles, pre-swizzled smem image.
// ---------------------------------------------------------------------------
__global__ void quantize_kernel(const float* __restrict__ w) {
    const float a = g_alpha;
    uint32_t id = blockIdx.x * 256 + threadIdx.x;   // < 86*65536
    uint32_t nb = id >> 16;           // 128-row block (0..85)
    uint32_t t = id & 65535;
    uint32_t kt = t >> 10;            // k chunk (0..63)
    uint32_t wv = t & 1023;
    uint32_t r = wv >> 3;             // row in tile (0..127)
    uint32_t c = wv & 7;              // 16B chunk in row (0..7)
    const float* src = w + ((size_t)(nb * 128 + r)) * IN_F + kt * 64 + c * 8;
    float4 v0 = *(const float4*)src;
    float4 v1 = *(const float4*)(src + 4);
    __half h[8];
    h[0] = __float2half_rn((v0.x > a) ? 1.0f : ((v0.x < -a) ? -1.0f : 0.0f));
    h[1] = __float2half_rn((v0.y > a) ? 1.0f : ((v0.y < -a) ? -1.0f : 0.0f));
    h[2] = __float2half_rn((v0.z > a) ? 1.0f : ((v0.z < -a) ? -1.0f : 0.0f));
    h[3] = __float2half_rn((v0.w > a) ? 1.0f : ((v0.w < -a) ? -1.0f : 0.0f));
    h[4] = __float2half_rn((v1.x > a) ? 1.0f : ((v1.x < -a) ? -1.0f : 0.0f));
    h[5] = __float2half_rn((v1.y > a) ? 1.0f : ((v1.y < -a) ? -1.0f : 0.0f));
    h[6] = __float2half_rn((v1.z > a) ? 1.0f : ((v1.z < -a) ? -1.0f : 0.0f));
    h[7] = __float2half_rn((v1.w > a) ? 1.0f : ((v1.w < -a) ? -1.0f : 0.0f));
    char* dst = (char*)g_q + (((size_t)nb * KTILES + kt) << 14) + swz128(r, c);
    *(uint4*)dst = *(const uint4*)h;
}

// ---------------------------------------------------------------------------
// Kernel 4: x -> fp16 tiles, pre-swizzled smem image.
// ---------------------------------------------------------------------------
__global__ void convert_x_kernel(const float* __restrict__ x) {
    uint32_t id = blockIdx.x * 256 + threadIdx.x;   // < 32*65536
    uint32_t mb = id >> 16;
    uint32_t t = id & 65535;
    uint32_t kt = t >> 10;
    uint32_t wv = t & 1023;
    uint32_t r = wv >> 3;
    uint32_t c = wv & 7;
    const float* src = x + ((size_t)(mb * 128 + r)) * IN_F + kt * 64 + c * 8;
    float4 v0 = *(const float4*)src;
    float4 v1 = *(const float4*)(src + 4);
    __half h[8];
    h[0] = __float2half_rn(v0.x); h[1] = __float2half_rn(v0.y);
    h[2] = __float2half_rn(v0.z); h[3] = __float2half_rn(v0.w);
    h[4] = __float2half_rn(v1.x); h[5] = __float2half_rn(v1.y);
    h[6] = __float2half_rn(v1.z); h[7] = __float2half_rn(v1.w);
    char* dst = (char*)g_xh + (((size_t)mb * KTILES + kt) << 14) + swz128(r, c);
    *(uint4*)dst = *(const uint4*)h;
}

// ---------------------------------------------------------------------------
// Kernel 5: fp16 HMMA GEMM (R11 mainloop) with full/empty mbarrier
// pipeline instead of per-kt __syncthreads. Producer = lane 0 of warp 0.
// out[m, n] = (sum_k xh[m,k] * q[n,k]) * scale[n] + bias[n]
// ---------------------------------------------------------------------------
__global__ void __launch_bounds__(256, 2)
gemm_kernel(float* __restrict__ out, const float* __restrict__ scale,
            const float* __restrict__ bias) {
    extern __shared__ __align__(128) char smem[];
    __shared__ __align__(8) uint64_t full_s[STAGES];
    __shared__ __align__(8) uint64_t empty_s[STAGES];
    const uint32_t sb = smem_u32(smem);
    uint32_t fullb[STAGES], emptyb[STAGES];
#pragma unroll
    for (int s = 0; s < STAGES; s++) {
        fullb[s] = smem_u32(&full_s[s]);
        emptyb[s] = smem_u32(&empty_s[s]);
    }

    const int tid = threadIdx.x;
    const int lane = tid & 31;
    const int wid = tid >> 5;
    const int warp_m = (wid & 1) * 64;
    const int warp_n = (wid >> 1) * 32;

    const int m0 = blockIdx.x * BM;   // m fastest -> q n-tiles L2-shared
    const int n0 = blockIdx.y * BN;

    const char* aT = (const char*)g_xh + ((size_t)blockIdx.x * KTILES << 14);
    const char* bT = (const char*)g_q + ((size_t)blockIdx.y * KTILES << 14);

    // ldsm swizzled offsets at ks=0; per-ks address = base ^ (ks<<5).
    uint32_t offA[4], offB[2];
#pragma unroll
    for (int mt = 0; mt < 4; mt++)
        offA[mt] = swz128((uint32_t)(warp_m + mt * 16 + (lane & 15)),
                          (uint32_t)(lane >> 4));
#pragma unroll
    for (int ng = 0; ng < 2; ng++)
        offB[ng] = A_TILE_BYTES +
                   swz128((uint32_t)(warp_n + ng * 16 + ((lane >> 4) << 3) + (lane & 7)),
                          (uint32_t)((lane >> 3) & 1));

    float acc[4][4][4];
#pragma unroll
    for (int mt = 0; mt < 4; mt++)
#pragma unroll
        for (int nt = 0; nt < 4; nt++)
#pragma unroll
            for (int j = 0; j < 4; j++) acc[mt][nt][j] = 0.0f;

    if (tid == 0) {
#pragma unroll
        for (int s = 0; s < STAGES; s++) {
            MBAR_INIT(fullb[s], 1);    // completed by expect_tx transactions
            MBAR_INIT(emptyb[s], 8);   // one arrive per warp
        }
    }
    __syncthreads();   // barriers visible to all warps (once, not per-kt)

    // Producer cursor (lane 0 of warp 0): stage ps, phase pp (starts 1 so the
    // first STAGES empty-waits pass immediately).
    int ps = 0; uint32_t pp = 1;
    if (tid == 0) {
        FENCE_PROXY_ASYNC();
#pragma unroll
        for (int i = 0; i < STAGES - 1; i++) {   // prologue: chunks 0,1
            mbar_wait(emptyb[ps], pp);
            MBAR_EXPECT_TX(fullb[ps], STAGE_BYTES);
            bulk_cp(sb + ps * STAGE_BYTES, aT + ((size_t)i << 14),
                    A_TILE_BYTES, fullb[ps]);
            bulk_cp(sb + ps * STAGE_BYTES + A_TILE_BYTES, bT + ((size_t)i << 14),
                    B_TILE_BYTES, fullb[ps]);
            if (++ps == STAGES) { ps = 0; pp ^= 1; }
        }
    }

    // Consumer cursor: stage cs, phase cp.
    int cs = 0; uint32_t cp = 0;
    for (int kt = 0; kt < KTILES; kt++) {
        // Producer: issue load for chunk kt+2 after its stage is drained.
        if (tid == 0 && kt + STAGES - 1 < KTILES) {
            const int kn = kt + STAGES - 1;
            mbar_wait(emptyb[ps], pp);
            FENCE_PROXY_ASYNC();
            MBAR_EXPECT_TX(fullb[ps], STAGE_BYTES);
            bulk_cp(sb + ps * STAGE_BYTES, aT + ((size_t)kn << 14),
                    A_TILE_BYTES, fullb[ps]);
            bulk_cp(sb + ps * STAGE_BYTES + A_TILE_BYTES,
                    bT + ((size_t)kn << 14), B_TILE_BYTES, fullb[ps]);
            if (++ps == STAGES) { ps = 0; pp ^= 1; }
        }

        mbar_wait(fullb[cs], cp);
        const uint32_t stage = sb + cs * STAGE_BYTES;

#pragma unroll 1
        for (int ks = 0; ks < 4; ks++) {
            const uint32_t kx = (uint32_t)(ks << 5);
            uint32_t af[4][4];
            uint32_t bf[4][2];
#pragma unroll
            for (int mt = 0; mt < 4; mt++)
                ldsm_x4(af[mt][0], af[mt][1], af[mt][2], af[mt][3],
                        stage + (offA[mt] ^ kx));
#pragma unroll
            for (int ng = 0; ng < 2; ng++) {
                uint32_t r0, r1, r2, r3;
                ldsm_x4(r0, r1, r2, r3, stage + (offB[ng] ^ kx));
                bf[2 * ng + 0][0] = r0; bf[2 * ng + 0][1] = r1;
                bf[2 * ng + 1][0] = r2; bf[2 * ng + 1][1] = r3;
            }
#pragma unroll
            for (int mt = 0; mt < 4; mt++)
#pragma unroll
                for (int nt = 0; nt < 4; nt++)
                    mma16816(acc[mt][nt][0], acc[mt][nt][1],
                             acc[mt][nt][2], acc[mt][nt][3],
                             af[mt][0], af[mt][1], af[mt][2], af[mt][3],
                             bf[nt][0], bf[nt][1]);
        }

        // This warp is done reading stage cs for chunk kt.
        if (lane == 0) MBAR_ARRIVE(emptyb[cs]);
        if (++cs == STAGES) { cs = 0; cp ^= 1; }
    }

    // Epilogue: scale + bias, direct fp32 stores.
#pragma unroll
    for (int nt = 0; nt < 4; nt++) {
        const int c = n0 + warp_n + nt * 8 + (lane & 3) * 2;
        const float s0 = __ldg(scale + c), s1 = __ldg(scale + c + 1);
        const float b0 = __ldg(bias + c), b1 = __ldg(bias + c + 1);
#pragma unroll
        for (int mt = 0; mt < 4; mt++) {
            const int r0 = m0 + warp_m + mt * 16 + (lane >> 2);
            float2 v0 = {acc[mt][nt][0] * s0 + b0, acc[mt][nt][1] * s1 + b1};
            float2 v1 = {acc[mt][nt][2] * s0 + b0, acc[mt][nt][3] * s1 + b1};
            *(float2*)(out + (size_t)r0 * OUT_F + c) = v0;
            *(float2*)(out + (size_t)(r0 + 8) * OUT_F + c) = v1;
        }
    }
}

// ---------------------------------------------------------------------------
// kernel_launch
// ---------------------------------------------------------------------------
extern "C" void kernel_launch(void* const* d_in, const int* in_sizes, int n_in,
                              void* d_out, int out_size) {
    const float* x      = (const float*)d_in[0];  // (4096, 4096)
    const float* weight = (const float*)d_in[1];  // (11008, 4096)
    const float* scale  = (const float*)d_in[2];  // (11008, 1)
    const float* bias   = (const float*)d_in[3];  // (11008,)
    float* out = (float*)d_out;                   // (4096, 11008)
    (void)in_sizes; (void)n_in; (void)out_size;

    reduce_abs_kernel<<<1024, 256>>>(weight);
    finalize_alpha_kernel<<<1, 256>>>();
    quantize_kernel<<<(OUT_F / 128) * 256, 256>>>(weight);   // 86*65536 chunks
    convert_x_kernel<<<(TOKENS / 128) * 256, 256>>>(x);      // 32*65536 chunks

    cudaFuncSetAttribute(gemm_kernel,
                         cudaFuncAttributeMaxDynamicSharedMemorySize, SMEM_TOTAL);
    dim3 grid(TOKENS / BM, OUT_F / BN);  // (32, 86)
    gemm_kernel<<<grid, 256, SMEM_TOTAL>>>(out, scale, bias);
}

// round 17
// speedup vs baseline: 1.0974x; 1.0778x over previous
#include <cuda_runtime.h>
#include <cuda_fp16.h>
#include <cstdint>
#include <cstddef>

// ---------------------------------------------------------------------------
// Problem constants
// ---------------------------------------------------------------------------
#define TOKENS 4096   // M
#define IN_F   4096   // K
#define OUT_F  11008  // N

// GEMM tiling: CTA 128x128, 8 warps (2m x 4n), warp tile m64n32, 2 CTAs/SM.
// R11 mainloop (bulk-copy + per-kt __syncthreads, 3-stage ring) — proven 987us.
#define BM 128
#define BN 128
#define BK 64
#define KTILES (IN_F / BK)   // 64
#define STAGES 3

#define A_TILE_BYTES 16384                    // 128 rows x 128 B
#define B_TILE_BYTES 16384
#define STAGE_BYTES  (A_TILE_BYTES + B_TILE_BYTES)      // 32768
#define SMEM_TOTAL   (STAGES * STAGE_BYTES)             // 98304 -> 2 CTAs/SM

// ---------------------------------------------------------------------------
// Device scratch (static — no cudaMalloc anywhere)
// Tiled layout: [row_block][kt][16KB tile], tile = swizzled smem image.
// ---------------------------------------------------------------------------
__device__ __half  g_q[(size_t)OUT_F * IN_F];    // ternary weights, tiled+swizzled
__device__ __half  g_xh[(size_t)TOKENS * IN_F];  // fp16(x), tiled+swizzled
__device__ double  g_partial[1024];
__device__ float   g_alpha;

// ---------------------------------------------------------------------------
// PTX helpers (baseline compute_103 — cp.async.bulk + mbarrier are sm_90 PTX)
// ---------------------------------------------------------------------------
__device__ __forceinline__ uint32_t smem_u32(const void* p) {
    uint32_t a;
    asm("{ .reg .u64 t; cvta.to.shared.u64 t, %1; cvt.u32.u64 %0, t; }"
        : "=r"(a) : "l"(p));
    return a;
}

__device__ __forceinline__ void bulk_cp(uint32_t dst, const void* src,
                                        uint32_t bytes, uint32_t mbar) {
    asm volatile(
        "{ .reg .u64 g; cvta.to.global.u64 g, %1; "
        "cp.async.bulk.shared::cta.global.mbarrier::complete_tx::bytes "
        "[%0], [g], %2, [%3]; }"
        :: "r"(dst), "l"(src), "r"(bytes), "r"(mbar) : "memory");
}

#define MBAR_INIT(a, c) \
    asm volatile("mbarrier.init.shared.b64 [%0], %1;" :: "r"(a), "r"((uint32_t)(c)) : "memory")
#define MBAR_EXPECT_TX(a, b) \
    asm volatile("mbarrier.arrive.expect_tx.shared.b64 _, [%0], %1;" \
                 :: "r"(a), "r"((uint32_t)(b)) : "memory")
#define FENCE_PROXY_ASYNC() \
    asm volatile("fence.proxy.async.shared::cta;" ::: "memory")

__device__ __forceinline__ void mbar_wait(uint32_t addr, uint32_t parity) {
    asm volatile(
        "{\n\t"
        ".reg .pred P;\n\t"
        "WL_%=:\n\t"
        "mbarrier.try_wait.parity.acquire.cta.shared::cta.b64 P, [%0], %1, 0x989680;\n\t"
        "@P bra WD_%=;\n\t"
        "bra WL_%=;\n\t"
        "WD_%=:\n\t"
        "}"
        :: "r"(addr), "r"(parity) : "memory");
}

__device__ __forceinline__ void ldsm_x4(uint32_t& r0, uint32_t& r1,
                                        uint32_t& r2, uint32_t& r3, uint32_t a) {
    asm volatile("ldmatrix.sync.aligned.m8n8.x4.shared.b16 {%0,%1,%2,%3}, [%4];"
                 : "=r"(r0), "=r"(r1), "=r"(r2), "=r"(r3) : "r"(a));
}

__device__ __forceinline__ void mma16816(float& c0, float& c1, float& c2, float& c3,
                                         uint32_t a0, uint32_t a1, uint32_t a2, uint32_t a3,
                                         uint32_t b0, uint32_t b1) {
    asm volatile(
        "mma.sync.aligned.m16n8k16.row.col.f32.f16.f16.f32 "
        "{%0,%1,%2,%3}, {%4,%5,%6,%7}, {%8,%9}, {%0,%1,%2,%3};"
        : "+f"(c0), "+f"(c1), "+f"(c2), "+f"(c3)
        : "r"(a0), "r"(a1), "r"(a2), "r"(a3), "r"(b0), "r"(b1));
}

// SW128 swizzle for 128-byte rows: 16B chunk c (0..7), row r.
__device__ __forceinline__ uint32_t swz128(uint32_t row, uint32_t c) {
    return row * 128u + ((c ^ (row & 7u)) << 4);
}

// ---------------------------------------------------------------------------
// Kernel 1: deterministic |W| partial sums (fp64 accumulators)
// (byte-identical to R11 — summation order fixed so alpha is bit-identical)
// ---------------------------------------------------------------------------
__global__ void reduce_abs_kernel(const float* __restrict__ w) {
    __shared__ double sh[256];
    const size_t n4 = (size_t)OUT_F * IN_F / 4;
    const float4* w4 = (const float4*)w;
    double acc = 0.0;
    for (size_t i = (size_t)blockIdx.x * 256 + threadIdx.x; i < n4;
         i += (size_t)1024 * 256) {
        float4 v = w4[i];
        acc += (double)fabsf(v.x) + (double)fabsf(v.y) +
               (double)fabsf(v.z) + (double)fabsf(v.w);
    }
    int tid = threadIdx.x;
    sh[tid] = acc;
    __syncthreads();
    for (int s = 128; s > 0; s >>= 1) {
        if (tid < s) sh[tid] += sh[tid + s];
        __syncthreads();
    }
    if (tid == 0) g_partial[blockIdx.x] = sh[0];
}

__global__ void finalize_alpha_kernel() {
    __shared__ double sh[256];
    int tid = threadIdx.x;
    double a = g_partial[tid] + g_partial[tid + 256] +
               g_partial[tid + 512] + g_partial[tid + 768];
    sh[tid] = a;
    __syncthreads();
    for (int s = 128; s > 0; s >>= 1) {
        if (tid < s) sh[tid] += sh[tid + s];
        __syncthreads();
    }
    if (tid == 0) g_alpha = (float)(sh[0] / ((double)OUT_F * (double)IN_F));
}

// ---------------------------------------------------------------------------
// Kernel 3: ternary quantize W -> fp16 tiles, pre-swizzled smem image.
// TWO independent 16B chunks per thread (rows r and r+64) for MLP.
// ---------------------------------------------------------------------------
__device__ __forceinline__ void quant8(const float* __restrict__ src,
                                       float a, __half* h) {
    float4 v0 = *(const float4*)src;
    float4 v1 = *(const float4*)(src + 4);
    h[0] = __float2half_rn((v0.x > a) ? 1.0f : ((v0.x < -a) ? -1.0f : 0.0f));
    h[1] = __float2half_rn((v0.y > a) ? 1.0f : ((v0.y < -a) ? -1.0f : 0.0f));
    h[2] = __float2half_rn((v0.z > a) ? 1.0f : ((v0.z < -a) ? -1.0f : 0.0f));
    h[3] = __float2half_rn((v0.w > a) ? 1.0f : ((v0.w < -a) ? -1.0f : 0.0f));
    h[4] = __float2half_rn((v1.x > a) ? 1.0f : ((v1.x < -a) ? -1.0f : 0.0f));
    h[5] = __float2half_rn((v1.y > a) ? 1.0f : ((v1.y < -a) ? -1.0f : 0.0f));
    h[6] = __float2half_rn((v1.z > a) ? 1.0f : ((v1.z < -a) ? -1.0f : 0.0f));
    h[7] = __float2half_rn((v1.w > a) ? 1.0f : ((v1.w < -a) ? -1.0f : 0.0f));
}

__global__ void quantize_kernel(const float* __restrict__ w) {
    const float a = g_alpha;
    uint32_t id = blockIdx.x * 256 + threadIdx.x;   // < 86*32768
    uint32_t nb = id >> 15;           // 128-row block (0..85)
    uint32_t t = id & 32767;
    uint32_t kt = t >> 9;             // k chunk (0..63)
    uint32_t wv = t & 511;
    uint32_t r = wv >> 3;             // row in tile (0..63); second row r+64
    uint32_t c = wv & 7;              // 16B chunk in row (0..7)
    const float* s0 = w + ((size_t)(nb * 128 + r)) * IN_F + kt * 64 + c * 8;
    const float* s1 = s0 + (size_t)64 * IN_F;
    __half h0[8], h1[8];
    quant8(s0, a, h0);
    quant8(s1, a, h1);
    char* base = (char*)g_q + (((size_t)nb * KTILES + kt) << 14);
    *(uint4*)(base + swz128(r, c)) = *(const uint4*)h0;
    *(uint4*)(base + swz128(r + 64, c)) = *(const uint4*)h1;
}

// ---------------------------------------------------------------------------
// Kernel 4: x -> fp16 tiles, pre-swizzled smem image. Two chunks per thread.
// ---------------------------------------------------------------------------
__device__ __forceinline__ void cvt8(const float* __restrict__ src, __half* h) {
    float4 v0 = *(const float4*)src;
    float4 v1 = *(const float4*)(src + 4);
    h[0] = __float2half_rn(v0.x); h[1] = __float2half_rn(v0.y);
    h[2] = __float2half_rn(v0.z); h[3] = __float2half_rn(v0.w);
    h[4] = __float2half_rn(v1.x); h[5] = __float2half_rn(v1.y);
    h[6] = __float2half_rn(v1.z); h[7] = __float2half_rn(v1.w);
}

__global__ void convert_x_kernel(const float* __restrict__ x) {
    uint32_t id = blockIdx.x * 256 + threadIdx.x;   // < 32*32768
    uint32_t mb = id >> 15;
    uint32_t t = id & 32767;
    uint32_t kt = t >> 9;
    uint32_t wv = t & 511;
    uint32_t r = wv >> 3;
    uint32_t c = wv & 7;
    const float* s0 = x + ((size_t)(mb * 128 + r)) * IN_F + kt * 64 + c * 8;
    const float* s1 = s0 + (size_t)64 * IN_F;
    __half h0[8], h1[8];
    cvt8(s0, h0);
    cvt8(s1, h1);
    char* base = (char*)g_xh + (((size_t)mb * KTILES + kt) << 14);
    *(uint4*)(base + swz128(r, c)) = *(const uint4*)h0;
    *(uint4*)(base + swz128(r + 64, c)) = *(const uint4*)h1;
}

// ---------------------------------------------------------------------------
// Kernel 5: fp16 HMMA GEMM — R11 mainloop verbatim (987us proven).
// Single-thread cp.async.bulk of pre-swizzled 16KB tiles, mbarrier completion,
// per-kt __syncthreads, 3-stage ring, distance-2 prefetch.
// out[m, n] = (sum_k xh[m,k] * q[n,k]) * scale[n] + bias[n]
// ---------------------------------------------------------------------------
__global__ void __launch_bounds__(256, 2)
gemm_kernel(float* __restrict__ out, const float* __restrict__ scale,
            const float* __restrict__ bias) {
    extern __shared__ __align__(128) char smem[];
    __shared__ __align__(8) uint64_t mbar_s[STAGES];
    const uint32_t sb = smem_u32(smem);
    uint32_t mb[STAGES];
#pragma unroll
    for (int s = 0; s < STAGES; s++) mb[s] = smem_u32(&mbar_s[s]);

    const int tid = threadIdx.x;
    const int lane = tid & 31;
    const int wid = tid >> 5;
    const int warp_m = (wid & 1) * 64;
    const int warp_n = (wid >> 1) * 32;

    const int m0 = blockIdx.x * BM;   // m fastest -> q n-tiles L2-shared
    const int n0 = blockIdx.y * BN;

    const char* aT = (const char*)g_xh + ((size_t)blockIdx.x * KTILES << 14);
    const char* bT = (const char*)g_q + ((size_t)blockIdx.y * KTILES << 14);

    // ldsm swizzled offsets at ks=0; per-ks address = base ^ (ks<<5).
    uint32_t offA[4], offB[2];
#pragma unroll
    for (int mt = 0; mt < 4; mt++)
        offA[mt] = swz128((uint32_t)(warp_m + mt * 16 + (lane & 15)),
                          (uint32_t)(lane >> 4));
#pragma unroll
    for (int ng = 0; ng < 2; ng++)
        offB[ng] = A_TILE_BYTES +
                   swz128((uint32_t)(warp_n + ng * 16 + ((lane >> 4) << 3) + (lane & 7)),
                          (uint32_t)((lane >> 3) & 1));

    float acc[4][4][4];
#pragma unroll
    for (int mt = 0; mt < 4; mt++)
#pragma unroll
        for (int nt = 0; nt < 4; nt++)
#pragma unroll
            for (int j = 0; j < 4; j++) acc[mt][nt][j] = 0.0f;

    if (tid == 0) {
#pragma unroll
        for (int s = 0; s < STAGES; s++) MBAR_INIT(mb[s], 1);
    }
    __syncthreads();

    // Prologue: stages 0..1 <- chunks 0..1
    if (tid == 0) {
        FENCE_PROXY_ASYNC();
#pragma unroll
        for (int s = 0; s < STAGES - 1; s++) {
            MBAR_EXPECT_TX(mb[s], STAGE_BYTES);
            bulk_cp(sb + s * STAGE_BYTES, aT + ((size_t)s << 14),
                    A_TILE_BYTES, mb[s]);
            bulk_cp(sb + s * STAGE_BYTES + A_TILE_BYTES, bT + ((size_t)s << 14),
                    B_TILE_BYTES, mb[s]);
        }
    }

    int s_comp = 0, s_load = STAGES - 1;
    uint32_t phase = 0;
    for (int kt = 0; kt < KTILES; kt++) {
        __syncthreads();   // all warps done reading stage s_load (from kt-1)

        if (tid == 0 && kt + 2 < KTILES) {
            FENCE_PROXY_ASYNC();
            MBAR_EXPECT_TX(mb[s_load], STAGE_BYTES);
            bulk_cp(sb + s_load * STAGE_BYTES, aT + ((size_t)(kt + 2) << 14),
                    A_TILE_BYTES, mb[s_load]);
            bulk_cp(sb + s_load * STAGE_BYTES + A_TILE_BYTES,
                    bT + ((size_t)(kt + 2) << 14), B_TILE_BYTES, mb[s_load]);
        }
        if (++s_load == STAGES) s_load = 0;

        mbar_wait(mb[s_comp], phase);

        const uint32_t stage = sb + s_comp * STAGE_BYTES;
        if (++s_comp == STAGES) { s_comp = 0; phase ^= 1; }

#pragma unroll 1
        for (int ks = 0; ks < 4; ks++) {
            const uint32_t kx = (uint32_t)(ks << 5);
            uint32_t af[4][4];
            uint32_t bf[4][2];
#pragma unroll
            for (int mt = 0; mt < 4; mt++)
                ldsm_x4(af[mt][0], af[mt][1], af[mt][2], af[mt][3],
                        stage + (offA[mt] ^ kx));
#pragma unroll
            for (int ng = 0; ng < 2; ng++) {
                uint32_t r0, r1, r2, r3;
                ldsm_x4(r0, r1, r2, r3, stage + (offB[ng] ^ kx));
                bf[2 * ng + 0][0] = r0; bf[2 * ng + 0][1] = r1;
                bf[2 * ng + 1][0] = r2; bf[2 * ng + 1][1] = r3;
            }
#pragma unroll
            for (int mt = 0; mt < 4; mt++)
#pragma unroll
                for (int nt = 0; nt < 4; nt++)
                    mma16816(acc[mt][nt][0], acc[mt][nt][1],
                             acc[mt][nt][2], acc[mt][nt][3],
                             af[mt][0], af[mt][1], af[mt][2], af[mt][3],
                             bf[nt][0], bf[nt][1]);
        }
    }

    // Epilogue: scale + bias, direct fp32 stores.
#pragma unroll
    for (int nt = 0; nt < 4; nt++) {
        const int c = n0 + warp_n + nt * 8 + (lane & 3) * 2;
        const float s0 = __ldg(scale + c), s1 = __ldg(scale + c + 1);
        const float b0 = __ldg(bias + c), b1 = __ldg(bias + c + 1);
#pragma unroll
        for (int mt = 0; mt < 4; mt++) {
            const int r0 = m0 + warp_m + mt * 16 + (lane >> 2);
            float2 v0 = {acc[mt][nt][0] * s0 + b0, acc[mt][nt][1] * s1 + b1};
            float2 v1 = {acc[mt][nt][2] * s0 + b0, acc[mt][nt][3] * s1 + b1};
            *(float2*)(out + (size_t)r0 * OUT_F + c) = v0;
            *(float2*)(out + (size_t)(r0 + 8) * OUT_F + c) = v1;
        }
    }
}

// ---------------------------------------------------------------------------
// kernel_launch
// ---------------------------------------------------------------------------
extern "C" void kernel_launch(void* const* d_in, const int* in_sizes, int n_in,
                              void* d_out, int out_size) {
    const float* x      = (const float*)d_in[0];  // (4096, 4096)
    const float* weight = (const float*)d_in[1];  // (11008, 4096)
    const float* scale  = (const float*)d_in[2];  // (11008, 1)
    const float* bias   = (const float*)d_in[3];  // (11008,)
    float* out = (float*)d_out;                   // (4096, 11008)
    (void)in_sizes; (void)n_in; (void)out_size;

    reduce_abs_kernel<<<1024, 256>>>(weight);
    finalize_alpha_kernel<<<1, 256>>>();
    quantize_kernel<<<(OUT_F / 128) * 128, 256>>>(weight);   // 86*32768 / 256
    convert_x_kernel<<<(TOKENS / 128) * 128, 256>>>(x);      // 32*32768 / 256

    cudaFuncSetAttribute(gemm_kernel,
                         cudaFuncAttributeMaxDynamicSharedMemorySize, SMEM_TOTAL);
    dim3 grid(TOKENS / BM, OUT_F / BN);  // (32, 86)
    gemm_kernel<<<grid, 256, SMEM_TOTAL>>>(out, scale, bias);
}